// round 1
// baseline (speedup 1.0000x reference)
#include <cuda_runtime.h>

// Problem constants (fixed by the reference)
#define NN 100000
#define NE 600000
// dims: IN=128, L1=96, L2=64, OUT=32

// ---------------- device scratch (no allocations allowed) ----------------
__device__ int   g_cnt[NN];       // in-degree (w/o self loop)
__device__ int   g_rowptr[NN];    // CSR row starts (exclusive scan of g_cnt)
__device__ int   g_cur[NN];       // fill cursors
__device__ int   g_col[NE];       // CSR columns (src of each in-edge)
__device__ int   g_bsum[256];     // scan spine
__device__ float g_dinv[NN];      // 1/deg
__device__ float g_dis[NN];       // rsqrt(deg)
__device__ float g_xa[(size_t)NN * 128];  // aggregated x
__device__ float g_h1[(size_t)NN * 96];   // layer1 output
__device__ float g_ha[(size_t)NN * 96];   // aggregated h1
__device__ float g_h2[(size_t)NN * 64];   // layer2 output
__device__ float g_ms[(size_t)NN * 64];   // dis-scaled head projections
__device__ float g_Wml[64 * 64];          // [Wmu | Wls] concatenated cols

// ---------------- CSR build ----------------
__global__ void zero_kernel() {
    int i = blockIdx.x * blockDim.x + threadIdx.x;
    if (i < NN) { g_cnt[i] = 0; g_cur[i] = 0; }
}

__global__ void count_kernel(const int* __restrict__ dst) {
    int e = blockIdx.x * blockDim.x + threadIdx.x;
    if (e < NE) atomicAdd(&g_cnt[dst[e]], 1);
}

// 3-pass exclusive scan over g_cnt (2048 elems/block)
__global__ __launch_bounds__(256) void scan_sums_kernel() {
    __shared__ int sh[256];
    int tid = threadIdx.x;
    int base = blockIdx.x * 2048 + tid * 8;
    int s = 0;
#pragma unroll
    for (int j = 0; j < 8; j++) { int i = base + j; if (i < NN) s += g_cnt[i]; }
    sh[tid] = s; __syncthreads();
    for (int off = 128; off > 0; off >>= 1) {
        if (tid < off) sh[tid] += sh[tid + off];
        __syncthreads();
    }
    if (tid == 0) g_bsum[blockIdx.x] = sh[0];
}

__global__ void scan_spine_kernel(int nblk) {
    __shared__ int sh[256];
    int tid = threadIdx.x;
    int v = (tid < nblk) ? g_bsum[tid] : 0;
    sh[tid] = v; __syncthreads();
    for (int off = 1; off < 256; off <<= 1) {
        int t = (tid >= off) ? sh[tid - off] : 0;
        __syncthreads();
        sh[tid] += t;
        __syncthreads();
    }
    if (tid < nblk) g_bsum[tid] = sh[tid] - v;  // exclusive
}

__global__ __launch_bounds__(256) void scan_apply_kernel() {
    __shared__ int sh[256];
    int tid = threadIdx.x;
    int base = blockIdx.x * 2048 + tid * 8;
    int loc[8]; int s = 0;
#pragma unroll
    for (int j = 0; j < 8; j++) {
        int i = base + j;
        int v = (i < NN) ? g_cnt[i] : 0;
        loc[j] = s; s += v;
    }
    sh[tid] = s; __syncthreads();
    for (int off = 1; off < 256; off <<= 1) {
        int t = (tid >= off) ? sh[tid - off] : 0;
        __syncthreads();
        sh[tid] += t;
        __syncthreads();
    }
    int excl = sh[tid] - s;
    int off0 = g_bsum[blockIdx.x] + excl;
#pragma unroll
    for (int j = 0; j < 8; j++) {
        int i = base + j;
        if (i < NN) {
            g_rowptr[i] = off0 + loc[j];
            float deg = (float)(g_cnt[i] + 1);  // +1 self loop, >= 1 always
            g_dinv[i] = 1.0f / deg;
            g_dis[i]  = rsqrtf(deg);
        }
    }
}

__global__ void fill_kernel(const int* __restrict__ src, const int* __restrict__ dst) {
    int e = blockIdx.x * blockDim.x + threadIdx.x;
    if (e < NE) {
        int d = dst[e];
        int p = g_rowptr[d] + atomicAdd(&g_cur[d], 1);
        g_col[p] = src[e];
    }
}

__global__ void concatw_kernel(const float* __restrict__ Wmu, const float* __restrict__ Wls) {
    int i = blockIdx.x * blockDim.x + threadIdx.x;
    if (i < 64 * 64) {
        int k = i >> 6, n = i & 63;
        g_Wml[i] = (n < 32) ? Wmu[k * 32 + n] : Wls[k * 32 + (n - 32)];
    }
}

// ---------------- aggregations (CSR gather, float4 lanes) ----------------
// xa[i] = dinv[i] * (x[i] + sum_{j in N(i)} x[j]), width 128 -> warp per node
__global__ __launch_bounds__(256) void agg128_kernel(const float* __restrict__ x) {
    int node = (blockIdx.x * blockDim.x + threadIdx.x) >> 5;
    int lane = threadIdx.x & 31;
    if (node >= NN) return;
    const float4* in4 = (const float4*)x;
    float4 acc = in4[(size_t)node * 32 + lane];
    int beg = g_rowptr[node], cnt = g_cnt[node];
    for (int k = 0; k < cnt; k++) {
        int c = g_col[beg + k];
        float4 v = __ldg(&in4[(size_t)c * 32 + lane]);
        acc.x += v.x; acc.y += v.y; acc.z += v.z; acc.w += v.w;
    }
    float s = g_dinv[node];
    acc.x *= s; acc.y *= s; acc.z *= s; acc.w *= s;
    ((float4*)g_xa)[(size_t)node * 32 + lane] = acc;
}

// ha[i] = dinv[i] * (h1[i] + sum h1[j]), width 96 -> 24-thread groups
__global__ __launch_bounds__(192) void agg96_kernel() {
    int gid = blockIdx.x * 192 + threadIdx.x;
    int node = gid / 24, lane = gid % 24;
    if (node >= NN) return;
    const float4* in4 = (const float4*)g_h1;
    float4 acc = in4[(size_t)node * 24 + lane];
    int beg = g_rowptr[node], cnt = g_cnt[node];
    for (int k = 0; k < cnt; k++) {
        int c = g_col[beg + k];
        float4 v = __ldg(&in4[(size_t)c * 24 + lane]);
        acc.x += v.x; acc.y += v.y; acc.z += v.z; acc.w += v.w;
    }
    float s = g_dinv[node];
    acc.x *= s; acc.y *= s; acc.z *= s; acc.w *= s;
    ((float4*)g_ha)[(size_t)node * 24 + lane] = acc;
}

// out_mu/out_ls: out[i] = dis[i]*(ms[i] + sum ms[j]) + b, width 64 -> 16-thread groups
__global__ __launch_bounds__(256) void agg_out_kernel(const float* __restrict__ bmu,
                                                      const float* __restrict__ bls,
                                                      float* __restrict__ out) {
    int gid = blockIdx.x * 256 + threadIdx.x;
    int node = gid / 16, lane = gid % 16;
    if (node >= NN) return;
    const float4* in4 = (const float4*)g_ms;
    float4 acc = in4[(size_t)node * 16 + lane];
    int beg = g_rowptr[node], cnt = g_cnt[node];
    for (int k = 0; k < cnt; k++) {
        int c = g_col[beg + k];
        float4 v = __ldg(&in4[(size_t)c * 16 + lane]);
        acc.x += v.x; acc.y += v.y; acc.z += v.z; acc.w += v.w;
    }
    float s = g_dis[node];
    float4 b;
    float4* dst;
    if (lane < 8) {
        b = ((const float4*)bmu)[lane];
        dst = (float4*)out + (size_t)node * 8 + lane;
    } else {
        b = ((const float4*)bls)[lane - 8];
        dst = (float4*)out + (size_t)NN * 8 + (size_t)node * 8 + (lane - 8);
    }
    float4 r;
    r.x = fmaf(s, acc.x, b.x);
    r.y = fmaf(s, acc.y, b.y);
    r.z = fmaf(s, acc.z, b.z);
    r.w = fmaf(s, acc.w, b.w);
    *dst = r;
}

// ---------------- fp32 tiled GEMM (BM=128, BK=16, threads 256, 8 x NO/16 per thread) ----------------
template <int K, int NO>
__device__ __forceinline__ void gemm_accum(const float* __restrict__ A,
                                           const float* __restrict__ B,
                                           float (&acc)[8][NO / 16],
                                           float (*As)[132], float (*Bs)[NO],
                                           int m0, int tid, int ty, int tx) {
    constexpr int TN = NO / 16;
    for (int kt = 0; kt < K; kt += 16) {
        // load A tile [128 x 16] transposed into As[k][m]
#pragma unroll
        for (int p = 0; p < 2; p++) {
            int idx = tid + p * 256;
            int row = idx >> 2, k4 = idx & 3;
            float4 v = make_float4(0.f, 0.f, 0.f, 0.f);
            int gr = m0 + row;
            if (gr < NN) v = *(const float4*)(A + (size_t)gr * K + kt + k4 * 4);
            As[k4 * 4 + 0][row] = v.x;
            As[k4 * 4 + 1][row] = v.y;
            As[k4 * 4 + 2][row] = v.z;
            As[k4 * 4 + 3][row] = v.w;
        }
        // load B tile [16 x NO]
#pragma unroll
        for (int p = 0; p < TN; p++) {
            int idx = tid + p * 256;
            int kk = idx / NO, cc = idx % NO;
            Bs[kk][cc] = B[(size_t)(kt + kk) * NO + cc];
        }
        __syncthreads();
#pragma unroll
        for (int kk = 0; kk < 16; kk++) {
            float a[8];
            *(float4*)&a[0] = *(const float4*)&As[kk][ty * 8];
            *(float4*)&a[4] = *(const float4*)&As[kk][ty * 8 + 4];
            float b[TN];
#pragma unroll
            for (int j = 0; j < TN; j++) b[j] = Bs[kk][tx + j * 16];
#pragma unroll
            for (int i = 0; i < 8; i++)
#pragma unroll
                for (int j = 0; j < TN; j++)
                    acc[i][j] = fmaf(a[i], b[j], acc[i][j]);
        }
        __syncthreads();
    }
}

template <int K1, int K2, int NO, bool RELU, bool SCALE>
__device__ __forceinline__ void gemm_body(const float* __restrict__ A1, const float* __restrict__ B1,
                                          const float* __restrict__ A2, const float* __restrict__ B2,
                                          const float* __restrict__ bias, const float* __restrict__ scale,
                                          float* __restrict__ out) {
    __shared__ float As[16][132];
    __shared__ float Bs[16][NO];
    constexpr int TN = NO / 16;
    int tid = threadIdx.x, ty = tid >> 4, tx = tid & 15;
    int m0 = blockIdx.x * 128;
    float acc[8][TN];
#pragma unroll
    for (int i = 0; i < 8; i++)
#pragma unroll
        for (int j = 0; j < TN; j++) acc[i][j] = 0.f;

    gemm_accum<K1, NO>(A1, B1, acc, As, Bs, m0, tid, ty, tx);
    if constexpr (K2 > 0) gemm_accum<K2, NO>(A2, B2, acc, As, Bs, m0, tid, ty, tx);

#pragma unroll
    for (int i = 0; i < 8; i++) {
        int gr = m0 + ty * 8 + i;
        if (gr >= NN) continue;
        float sc = SCALE ? scale[gr] : 1.f;
#pragma unroll
        for (int j = 0; j < TN; j++) {
            int c = tx + j * 16;
            float v = acc[i][j];
            if (bias) v += bias[c];
            if (RELU) v = fmaxf(v, 0.f);
            if (SCALE) v *= sc;
            out[(size_t)gr * NO + c] = v;
        }
    }
}

__global__ __launch_bounds__(256) void gemm1_kernel(const float* __restrict__ x,
                                                    const float* __restrict__ W1,
                                                    const float* __restrict__ Wr1,
                                                    const float* __restrict__ b1) {
    // h1 = relu(xa@W1 + x@Wr1 + b1)
    gemm_body<128, 128, 96, true, false>(g_xa, W1, x, Wr1, b1, nullptr, g_h1);
}

__global__ __launch_bounds__(256) void gemm2_kernel(const float* __restrict__ W2,
                                                    const float* __restrict__ Wr2,
                                                    const float* __restrict__ b2) {
    // h2 = relu(ha@W2 + h1@Wr2 + b2)
    gemm_body<96, 96, 64, true, false>(g_ha, W2, g_h1, Wr2, b2, nullptr, g_h2);
}

__global__ __launch_bounds__(256) void gemm3_kernel() {
    // ms = dis * (h2 @ [Wmu | Wls])   (bias added after aggregation)
    gemm_body<64, 0, 64, false, true>(g_h2, g_Wml, nullptr, nullptr, nullptr, g_dis, g_ms);
}

// ---------------- launch ----------------
extern "C" void kernel_launch(void* const* d_in, const int* in_sizes, int n_in,
                              void* d_out, int out_size) {
    (void)in_sizes; (void)n_in; (void)out_size;
    const float* x   = (const float*)d_in[0];
    const int*   ei  = (const int*)d_in[1];
    const float* W1  = (const float*)d_in[2];
    const float* b1  = (const float*)d_in[3];
    const float* Wr1 = (const float*)d_in[4];
    const float* W2  = (const float*)d_in[5];
    const float* b2  = (const float*)d_in[6];
    const float* Wr2 = (const float*)d_in[7];
    const float* Wmu = (const float*)d_in[8];
    const float* bmu = (const float*)d_in[9];
    const float* Wls = (const float*)d_in[10];
    const float* bls = (const float*)d_in[11];
    float* out = (float*)d_out;

    const int* src = ei;         // edge_index[0]
    const int* dst = ei + NE;    // edge_index[1]

    int nblk = (NN + 2047) / 2048;  // 49
    int gemm_grid = (NN + 127) / 128;

    zero_kernel<<<(NN + 255) / 256, 256>>>();
    count_kernel<<<(NE + 255) / 256, 256>>>(dst);
    scan_sums_kernel<<<nblk, 256>>>();
    scan_spine_kernel<<<1, 256>>>(nblk);
    scan_apply_kernel<<<nblk, 256>>>();
    fill_kernel<<<(NE + 255) / 256, 256>>>(src, dst);
    concatw_kernel<<<16, 256>>>(Wmu, Wls);

    // Layer 1
    agg128_kernel<<<(NN + 7) / 8, 256>>>(x);
    gemm1_kernel<<<gemm_grid, 256>>>(x, W1, Wr1, b1);
    // Layer 2
    agg96_kernel<<<((size_t)NN * 24 + 191) / 192, 192>>>();
    gemm2_kernel<<<gemm_grid, 256>>>(W2, Wr2, b2);
    // Heads
    gemm3_kernel<<<gemm_grid, 256>>>();
    agg_out_kernel<<<((size_t)NN * 16 + 255) / 256, 256>>>(bmu, bls, out);
}

// round 10
// speedup vs baseline: 1.0096x; 1.0096x over previous
#include <cuda_runtime.h>

// Problem constants (fixed by the reference)
#define NN 100000
#define NE 600000
// dims: IN=128, L1=96, L2=64, OUT=32

// ---------------- device scratch (no allocations allowed) ----------------
__device__ int   g_cnt[NN];
__device__ int   g_rowptr[NN];
__device__ int   g_cur[NN];
__device__ int   g_col[NE];
__device__ int   g_bsum[256];
__device__ float g_dinv[NN];
__device__ float g_dis[NN];
// one arena, aliased across phases (all regions dead before reuse):
//   [0]        p1 = x@W1   (96)   -> later p2 = h1@W2 (64), later ms = h2@Wml (64)
//   [NN*96]    r1 = x@Wr1  (96)   -> later r2 = h1@Wr2 (64)
//   [NN*192]   h1          (96)   -> later h2 (64)
__device__ float g_buf[(size_t)NN * 96 * 3];
__device__ float g_Wml[64 * 64];          // [Wmu | Wls]

#define OFF1 ((size_t)NN * 96)
#define OFF2 ((size_t)NN * 96 * 2)

// ---------------- CSR build (verbatim round-1, proven) ----------------
__global__ void zero_kernel() {
    int i = blockIdx.x * blockDim.x + threadIdx.x;
    if (i < NN) { g_cnt[i] = 0; g_cur[i] = 0; }
}

__global__ void count_kernel(const int* __restrict__ dst) {
    int e = blockIdx.x * blockDim.x + threadIdx.x;
    if (e < NE) atomicAdd(&g_cnt[dst[e]], 1);
}

__global__ __launch_bounds__(256) void scan_sums_kernel() {
    __shared__ int sh[256];
    int tid = threadIdx.x;
    int base = blockIdx.x * 2048 + tid * 8;
    int s = 0;
#pragma unroll
    for (int j = 0; j < 8; j++) { int i = base + j; if (i < NN) s += g_cnt[i]; }
    sh[tid] = s; __syncthreads();
    for (int off = 128; off > 0; off >>= 1) {
        if (tid < off) sh[tid] += sh[tid + off];
        __syncthreads();
    }
    if (tid == 0) g_bsum[blockIdx.x] = sh[0];
}

__global__ void scan_spine_kernel(int nblk) {
    __shared__ int sh[256];
    int tid = threadIdx.x;
    int v = (tid < nblk) ? g_bsum[tid] : 0;
    sh[tid] = v; __syncthreads();
    for (int off = 1; off < 256; off <<= 1) {
        int t = (tid >= off) ? sh[tid - off] : 0;
        __syncthreads();
        sh[tid] += t;
        __syncthreads();
    }
    if (tid < nblk) g_bsum[tid] = sh[tid] - v;  // exclusive
}

__global__ __launch_bounds__(256) void scan_apply_kernel() {
    __shared__ int sh[256];
    int tid = threadIdx.x;
    int base = blockIdx.x * 2048 + tid * 8;
    int loc[8]; int s = 0;
#pragma unroll
    for (int j = 0; j < 8; j++) {
        int i = base + j;
        int v = (i < NN) ? g_cnt[i] : 0;
        loc[j] = s; s += v;
    }
    sh[tid] = s; __syncthreads();
    for (int off = 1; off < 256; off <<= 1) {
        int t = (tid >= off) ? sh[tid - off] : 0;
        __syncthreads();
        sh[tid] += t;
        __syncthreads();
    }
    int excl = sh[tid] - s;
    int off0 = g_bsum[blockIdx.x] + excl;
#pragma unroll
    for (int j = 0; j < 8; j++) {
        int i = base + j;
        if (i < NN) {
            g_rowptr[i] = off0 + loc[j];
            float deg = (float)(g_cnt[i] + 1);
            g_dinv[i] = 1.0f / deg;
            g_dis[i]  = rsqrtf(deg);
        }
    }
}

__global__ void fill_kernel(const int* __restrict__ src, const int* __restrict__ dst) {
    int e = blockIdx.x * blockDim.x + threadIdx.x;
    if (e < NE) {
        int d = dst[e];
        int p = g_rowptr[d] + atomicAdd(&g_cur[d], 1);
        g_col[p] = src[e];
    }
}

__global__ void concatw_kernel(const float* __restrict__ Wmu, const float* __restrict__ Wls) {
    int i = blockIdx.x * blockDim.x + threadIdx.x;
    if (i < 64 * 64) {
        int k = i >> 6, n = i & 63;
        g_Wml[i] = (n < 32) ? Wmu[k * 32 + n] : Wls[k * 32 + (n - 32)];
    }
}

// ------- fp32 tiled GEMM (verbatim round-1, proven): BM=128, BK=16, 256 thr, 8xTN per thread ----
template <int K, int NO>
__device__ __forceinline__ void gemm_accum(const float* __restrict__ A,
                                           const float* __restrict__ B,
                                           float (&acc)[8][NO / 16],
                                           float (*As)[132], float (*Bs)[NO],
                                           int m0, int tid, int ty, int tx) {
    constexpr int TN = NO / 16;
    for (int kt = 0; kt < K; kt += 16) {
        // load A tile [128 x 16] transposed into As[k][m]
#pragma unroll
        for (int p = 0; p < 2; p++) {
            int idx = tid + p * 256;
            int row = idx >> 2, k4 = idx & 3;
            float4 v = make_float4(0.f, 0.f, 0.f, 0.f);
            int gr = m0 + row;
            if (gr < NN) v = *(const float4*)(A + (size_t)gr * K + kt + k4 * 4);
            As[k4 * 4 + 0][row] = v.x;
            As[k4 * 4 + 1][row] = v.y;
            As[k4 * 4 + 2][row] = v.z;
            As[k4 * 4 + 3][row] = v.w;
        }
        // load B tile [16 x NO]
#pragma unroll
        for (int p = 0; p < TN; p++) {
            int idx = tid + p * 256;
            int kk = idx / NO, cc = idx % NO;
            Bs[kk][cc] = B[(size_t)(kt + kk) * NO + cc];
        }
        __syncthreads();
#pragma unroll
        for (int kk = 0; kk < 16; kk++) {
            float a[8];
            *(float4*)&a[0] = *(const float4*)&As[kk][ty * 8];
            *(float4*)&a[4] = *(const float4*)&As[kk][ty * 8 + 4];
            float b[TN];
#pragma unroll
            for (int j = 0; j < TN; j++) b[j] = Bs[kk][tx + j * 16];
#pragma unroll
            for (int i = 0; i < 8; i++)
#pragma unroll
                for (int j = 0; j < TN; j++)
                    acc[i][j] = fmaf(a[i], b[j], acc[i][j]);
        }
        __syncthreads();
    }
}

template <int K1, int NO, bool SCALE>
__device__ __forceinline__ void gemm_body(const float* __restrict__ A1, const float* __restrict__ B1,
                                          const float* __restrict__ scale,
                                          float* __restrict__ out) {
    __shared__ float As[16][132];
    __shared__ float Bs[16][NO];
    constexpr int TN = NO / 16;
    int tid = threadIdx.x, ty = tid >> 4, tx = tid & 15;
    int m0 = blockIdx.x * 128;
    float acc[8][TN];
#pragma unroll
    for (int i = 0; i < 8; i++)
#pragma unroll
        for (int j = 0; j < TN; j++) acc[i][j] = 0.f;

    gemm_accum<K1, NO>(A1, B1, acc, As, Bs, m0, tid, ty, tx);

#pragma unroll
    for (int i = 0; i < 8; i++) {
        int gr = m0 + ty * 8 + i;
        if (gr >= NN) continue;
        float sc = SCALE ? scale[gr] : 1.f;
#pragma unroll
        for (int j = 0; j < TN; j++) {
            int c = tx + j * 16;
            float v = acc[i][j];
            if (SCALE) v *= sc;
            out[(size_t)gr * NO + c] = v;
        }
    }
}

// layer 1: p1 = x@W1, r1 = x@Wr1   (K=128, NO=96)
__global__ __launch_bounds__(256) void gemm_p1_kernel(const float* __restrict__ x,
                                                      const float* __restrict__ W1) {
    gemm_body<128, 96, false>(x, W1, nullptr, g_buf);
}
__global__ __launch_bounds__(256) void gemm_r1_kernel(const float* __restrict__ x,
                                                      const float* __restrict__ Wr1) {
    gemm_body<128, 96, false>(x, Wr1, nullptr, g_buf + OFF1);
}
// layer 2: p2 = h1@W2, r2 = h1@Wr2 (K=96, NO=64); h1 lives at g_buf+OFF2
__global__ __launch_bounds__(256) void gemm_p2_kernel(const float* __restrict__ W2) {
    gemm_body<96, 64, false>(g_buf + OFF2, W2, nullptr, g_buf);
}
__global__ __launch_bounds__(256) void gemm_r2_kernel(const float* __restrict__ Wr2) {
    gemm_body<96, 64, false>(g_buf + OFF2, Wr2, nullptr, g_buf + OFF1);
}
// heads: ms = dis * (h2 @ [Wmu|Wls]); h2 at g_buf+OFF2, ms at g_buf
__global__ __launch_bounds__(256) void gemm3_kernel() {
    gemm_body<64, 64, true>(g_buf + OFF2, g_Wml, g_dis, g_buf);
}

// ------- combine: h = relu(dinv*agg(p) + r + b). Offsets into g_buf are template params -------
// (NEVER pass __device__ symbols from host code — that was the round-3..8 bug.)
template <int WIDTH, int TPB, size_t POFF, size_t ROFF, size_t HOFF>
__global__ __launch_bounds__(TPB) void agg_comb_kernel(const float* __restrict__ bias) {
    constexpr int LANES = WIDTH / 4;
    const float* p = g_buf + POFF;
    const float* r = g_buf + ROFF;
    float*       h = g_buf + HOFF;
    int gid = blockIdx.x * TPB + threadIdx.x;
    int node = gid / LANES, lane = gid % LANES;
    if (node >= NN) return;
    const float4* p4 = (const float4*)p;
    float4 acc = p4[(size_t)node * LANES + lane];
    int beg = g_rowptr[node], cnt = g_cnt[node];
    for (int k = 0; k < cnt; k++) {
        int c = g_col[beg + k];
        float4 v = __ldg(&p4[(size_t)c * LANES + lane]);
        acc.x += v.x; acc.y += v.y; acc.z += v.z; acc.w += v.w;
    }
    float s = g_dinv[node];
    float4 rr = ((const float4*)r)[(size_t)node * LANES + lane];
    float4 b  = __ldg((const float4*)bias + lane);
    float4 o;
    o.x = fmaxf(fmaf(s, acc.x, rr.x + b.x), 0.f);
    o.y = fmaxf(fmaf(s, acc.y, rr.y + b.y), 0.f);
    o.z = fmaxf(fmaf(s, acc.z, rr.z + b.z), 0.f);
    o.w = fmaxf(fmaf(s, acc.w, rr.w + b.w), 0.f);
    ((float4*)h)[(size_t)node * LANES + lane] = o;
}

// heads: out[i] = dis[i]*(ms[i] + sum ms[j]) + bias, split mu / ls halves (verbatim round-1)
__global__ __launch_bounds__(256) void agg_out_kernel(const float* __restrict__ bmu,
                                                      const float* __restrict__ bls,
                                                      float* __restrict__ out) {
    int gid = blockIdx.x * 256 + threadIdx.x;
    int node = gid >> 4, lane = gid & 15;
    if (node >= NN) return;
    const float4* in4 = (const float4*)g_buf;   // ms lives at g_buf
    float4 acc = in4[(size_t)node * 16 + lane];
    int beg = g_rowptr[node], cnt = g_cnt[node];
    for (int k = 0; k < cnt; k++) {
        int c = g_col[beg + k];
        float4 v = __ldg(&in4[(size_t)c * 16 + lane]);
        acc.x += v.x; acc.y += v.y; acc.z += v.z; acc.w += v.w;
    }
    float s = g_dis[node];
    float4 b;
    float4* dst;
    if (lane < 8) {
        b = ((const float4*)bmu)[lane];
        dst = (float4*)out + (size_t)node * 8 + lane;
    } else {
        b = ((const float4*)bls)[lane - 8];
        dst = (float4*)out + (size_t)NN * 8 + (size_t)node * 8 + (lane - 8);
    }
    float4 r;
    r.x = fmaf(s, acc.x, b.x);
    r.y = fmaf(s, acc.y, b.y);
    r.z = fmaf(s, acc.z, b.z);
    r.w = fmaf(s, acc.w, b.w);
    *dst = r;
}

// ---------------- launch ----------------
extern "C" void kernel_launch(void* const* d_in, const int* in_sizes, int n_in,
                              void* d_out, int out_size) {
    (void)in_sizes; (void)n_in; (void)out_size;
    const float* x   = (const float*)d_in[0];
    const int*   ei  = (const int*)d_in[1];
    const float* W1  = (const float*)d_in[2];
    const float* b1  = (const float*)d_in[3];
    const float* Wr1 = (const float*)d_in[4];
    const float* W2  = (const float*)d_in[5];
    const float* b2  = (const float*)d_in[6];
    const float* Wr2 = (const float*)d_in[7];
    const float* Wmu = (const float*)d_in[8];
    const float* bmu = (const float*)d_in[9];
    const float* Wls = (const float*)d_in[10];
    const float* bls = (const float*)d_in[11];
    float* out = (float*)d_out;

    const int* src = ei;         // edge_index[0]
    const int* dst = ei + NE;    // edge_index[1]

    int nblk = (NN + 2047) / 2048;  // 49
    int gemm_grid = (NN + 127) / 128;

    zero_kernel<<<(NN + 255) / 256, 256>>>();
    count_kernel<<<(NE + 255) / 256, 256>>>(dst);
    scan_sums_kernel<<<nblk, 256>>>();
    scan_spine_kernel<<<1, 256>>>(nblk);
    scan_apply_kernel<<<nblk, 256>>>();
    fill_kernel<<<(NE + 255) / 256, 256>>>(src, dst);
    concatw_kernel<<<16, 256>>>(Wmu, Wls);

    // Layer 1: p1 = x@W1, r1 = x@Wr1; h1 = relu(dinv*agg(p1) + r1 + b1)
    gemm_p1_kernel<<<gemm_grid, 256>>>(x, W1);
    gemm_r1_kernel<<<gemm_grid, 256>>>(x, Wr1);
    agg_comb_kernel<96, 192, 0, OFF1, OFF2><<<((size_t)NN * 24 + 191) / 192, 192>>>(b1);
    // Layer 2: p2 = h1@W2, r2 = h1@Wr2; h2 = relu(dinv*agg(p2) + r2 + b2)
    gemm_p2_kernel<<<gemm_grid, 256>>>(W2);
    gemm_r2_kernel<<<gemm_grid, 256>>>(Wr2);
    agg_comb_kernel<64, 256, 0, OFF1, OFF2><<<((size_t)NN * 16 + 255) / 256, 256>>>(b2);
    // Heads: ms = dis * (h2 @ [Wmu|Wls]); out = dis*agg(ms) + bias
    gemm3_kernel<<<gemm_grid, 256>>>();
    agg_out_kernel<<<((size_t)NN * 16 + 255) / 256, 256>>>(bmu, bls, out);
}